// round 1
// baseline (speedup 1.0000x reference)
#include <cuda_runtime.h>
#include <cstdint>

// 2D acoustic wave FDTD: 500 steps, 8 shots, 256x256 grid, 128 receivers/shot.
// One persistent kernel. Each shot = one 8-CTA cluster; fields live in SMEM,
// halo exchange + receiver sampling via DSMEM, one cluster barrier per step.

#define DT 0.001f
#define DX 10.0f

constexpr int NT   = 500;
constexpr int NS   = 8;
constexpr int NZ   = 256;
constexpr int NXC  = 256;
constexpr int NREC = 128;

constexpr int CSZ  = 8;            // CTAs per cluster (one cluster per shot)
constexpr int ROWS = NZ / CSZ;     // 32 rows per CTA
constexpr int NTHREADS = 512;
constexpr int COL4 = NXC / 4;      // 64 float4 columns
constexpr int RG   = NTHREADS / COL4;  // 8 row-groups
constexpr int RPT  = ROWS / RG;        // 4 rows per thread
constexpr int RPC  = NREC / CSZ;       // 16 receivers sampled per CTA

constexpr int BUF_ELEMS = ROWS * NXC;  // 8192 floats per buffer
constexpr int XS_PAD    = 512;
constexpr size_t SMEM_BYTES = (size_t)(2 * BUF_ELEMS + XS_PAD) * sizeof(float);

// ---------------------------------------------------------------- PTX helpers
__device__ __forceinline__ uint32_t cvta_smem(const void* p) {
    return (uint32_t)__cvta_generic_to_shared(p);
}
__device__ __forceinline__ uint32_t mapa_cluster(uint32_t laddr, uint32_t rank) {
    uint32_t r;
    asm("mapa.shared::cluster.u32 %0, %1, %2;" : "=r"(r) : "r"(laddr), "r"(rank));
    return r;
}
__device__ __forceinline__ float4 ld_dsmem_v4(uint32_t addr) {
    float4 v;
    asm volatile("ld.shared::cluster.v4.f32 {%0,%1,%2,%3}, [%4];"
                 : "=f"(v.x), "=f"(v.y), "=f"(v.z), "=f"(v.w) : "r"(addr));
    return v;
}
__device__ __forceinline__ float ld_dsmem_f32(uint32_t addr) {
    float v;
    asm volatile("ld.shared::cluster.f32 %0, [%1];" : "=f"(v) : "r"(addr));
    return v;
}
__device__ __forceinline__ void cluster_sync_() {
    asm volatile("barrier.cluster.arrive.aligned;" ::: "memory");
    asm volatile("barrier.cluster.wait.aligned;" ::: "memory");
}
__device__ __forceinline__ uint32_t cluster_rank_() {
    uint32_t r;
    asm("mov.u32 %0, %%cluster_ctarank;" : "=r"(r));
    return r;
}

// ---------------------------------------------------------------- kernel
__global__ void __cluster_dims__(CSZ, 1, 1) __launch_bounds__(NTHREADS, 1)
wave_kernel(const float* __restrict__ x,     // (NT, NS)
            const float* __restrict__ vp,    // (NZ, NXC)
            const int*   __restrict__ src,   // (NS, 2)
            const int*   __restrict__ rec,   // (NS, NREC, 2)
            float*       __restrict__ out)   // (NT, NS, NREC)
{
    extern __shared__ float sm[];
    float* buf0 = sm;
    float* buf1 = sm + BUF_ELEMS;
    float* xs   = sm + 2 * BUF_ELEMS;
    float* bufs[2] = { buf0, buf1 };

    const int tid  = threadIdx.x;
    const uint32_t rank = cluster_rank_();
    const int shot = blockIdx.x / CSZ;

    const int col4 = tid & (COL4 - 1);
    const int rg   = tid >> 6;          // tid / COL4
    const int lr0  = rg * RPT;          // first local row of this thread
    const int xcol = col4 * 4;

    // --- init: zero both buffers, stage x[:, shot] into smem -----------------
    for (int i = tid; i < BUF_ELEMS; i += NTHREADS) { buf0[i] = 0.f; buf1[i] = 0.f; }
    for (int i = tid; i < NT; i += NTHREADS) xs[i] = x[i * NS + shot];

    // --- c2 in registers -----------------------------------------------------
    float4 c2r[RPT];
    const float sc = DT / DX;
#pragma unroll
    for (int j = 0; j < RPT; j++) {
        const int g = (int)rank * ROWS + lr0 + j;
        float4 v = *(const float4*)(vp + g * NXC + xcol);
        float a = v.x * sc, b = v.y * sc, c = v.z * sc, d = v.w * sc;
        c2r[j] = make_float4(a * a, b * b, c * c, d * d);
    }

    // --- prev in registers (initially zero) ----------------------------------
    float4 pr[RPT];
#pragma unroll
    for (int j = 0; j < RPT; j++) pr[j] = make_float4(0.f, 0.f, 0.f, 0.f);

    // --- source ownership flags ----------------------------------------------
    const int sz = src[shot * 2 + 0];
    const int sx = src[shot * 2 + 1];
    const int sj = sz - ((int)rank * ROWS + lr0);
    const bool shere = (sj >= 0 && sj < RPT && sx >= xcol && sx < xcol + 4);
    const int scomp = sx - xcol;

    // --- DSMEM addresses: halo rows (both parities) --------------------------
    const uint32_t sa0 = cvta_smem(buf0);
    const uint32_t sa1 = cvta_smem(buf1);
    uint32_t nh_addr[2] = {0, 0}, sh_addr[2] = {0, 0};
    if (rg == 0 && rank > 0) {
        const uint32_t off = (uint32_t)((ROWS - 1) * NXC + xcol) * 4u;
        nh_addr[0] = mapa_cluster(sa0 + off, rank - 1);
        nh_addr[1] = mapa_cluster(sa1 + off, rank - 1);
    }
    if (rg == RG - 1 && rank < CSZ - 1) {
        const uint32_t off = (uint32_t)(xcol) * 4u;
        sh_addr[0] = mapa_cluster(sa0 + off, rank + 1);
        sh_addr[1] = mapa_cluster(sa1 + off, rank + 1);
    }

    // --- receiver addresses (both parities) ----------------------------------
    uint32_t rec_addr[2] = {0, 0};
    int outidx = 0;
    const bool is_rec = (tid < RPC);
    if (is_rec) {
        const int gi = shot * NREC + (int)rank * RPC + tid;
        const int rz = rec[gi * 2 + 0];
        const int rx = rec[gi * 2 + 1];
        const uint32_t owner = (uint32_t)(rz / ROWS);
        const uint32_t off = (uint32_t)((rz % ROWS) * NXC + rx) * 4u;
        rec_addr[0] = mapa_cluster(sa0 + off, owner);
        rec_addr[1] = mapa_cluster(sa1 + off, owner);
        outidx = shot * NREC + (int)rank * RPC + tid;
    }

    cluster_sync_();  // buffers zeroed cluster-wide before step 0

    // --- main time loop ------------------------------------------------------
    int p = 0;
    for (int t = 0; t < NT; t++) {
        const float* cur = bufs[p];
        float*       nxt = bufs[p ^ 1];
        int toff = t + 2; if (toff > NT - 1) toff = NT - 1;
        const float amp = xs[t] + xs[toff];

        // north row for the first row of this thread's strip
        float4 cN;
        if (lr0 == 0) {
            cN = (rank > 0) ? ld_dsmem_v4(nh_addr[p]) : make_float4(0.f, 0.f, 0.f, 0.f);
        } else {
            cN = *(const float4*)(cur + (lr0 - 1) * NXC + xcol);
        }
        float4 cC = *(const float4*)(cur + lr0 * NXC + xcol);

#pragma unroll
        for (int j = 0; j < RPT; j++) {
            const int lr = lr0 + j;
            float4 cS;
            if (lr == ROWS - 1) {
                cS = (rank < CSZ - 1) ? ld_dsmem_v4(sh_addr[p])
                                      : make_float4(0.f, 0.f, 0.f, 0.f);
            } else {
                cS = *(const float4*)(cur + (lr + 1) * NXC + xcol);
            }
            const float lft = (xcol > 0)        ? cur[lr * NXC + xcol - 1] : 0.f;
            const float rgt = (xcol + 4 < NXC)  ? cur[lr * NXC + xcol + 4] : 0.f;

            float4 lap;
            lap.x = cN.x + cS.x + lft  + cC.y - 4.f * cC.x;
            lap.y = cN.y + cS.y + cC.x + cC.z - 4.f * cC.y;
            lap.z = cN.z + cS.z + cC.y + cC.w - 4.f * cC.z;
            lap.w = cN.w + cS.w + cC.z + rgt  - 4.f * cC.w;

            float4 nv;
            nv.x = 2.f * cC.x - pr[j].x + c2r[j].x * lap.x;
            nv.y = 2.f * cC.y - pr[j].y + c2r[j].y * lap.y;
            nv.z = 2.f * cC.z - pr[j].z + c2r[j].z * lap.z;
            nv.w = 2.f * cC.w - pr[j].w + c2r[j].w * lap.w;

            if (shere && j == sj) {
                if      (scomp == 0) nv.x += amp;
                else if (scomp == 1) nv.y += amp;
                else if (scomp == 2) nv.z += amp;
                else                 nv.w += amp;
            }

            *(float4*)(nxt + lr * NXC + xcol) = nv;
            pr[j] = cC;
            cN = cC;
            cC = cS;
        }

        cluster_sync_();  // publish nxt cluster-wide (release/acquire)

        // sample receivers from the freshly written buffer (p^1).
        // Safe vs. step t+2 overwrite: the STG below depends on the load data,
        // and both precede this thread's arrive at the next barrier.
        if (is_rec) {
            const float v = ld_dsmem_f32(rec_addr[p ^ 1]);
            out[t * (NS * NREC) + outidx] = v;
        }

        p ^= 1;
    }
}

// ---------------------------------------------------------------- launch
extern "C" void kernel_launch(void* const* d_in, const int* in_sizes, int n_in,
                              void* d_out, int out_size)
{
    const float* x   = (const float*)d_in[0];
    const float* vp  = (const float*)d_in[1];
    const int*   src = (const int*)d_in[2];
    const int*   rec = (const int*)d_in[3];
    float*       out = (float*)d_out;

    cudaFuncSetAttribute((const void*)wave_kernel,
                         cudaFuncAttributeMaxDynamicSharedMemorySize,
                         (int)SMEM_BYTES);

    wave_kernel<<<NS * CSZ, NTHREADS, SMEM_BYTES>>>(x, vp, src, rec, out);
}